// round 1
// baseline (speedup 1.0000x reference)
#include <cuda_runtime.h>
#include <cuda_bf16.h>
#include <cstdint>

#define BB   8
#define NP   4096
#define KNN  20
#define CH   64
#define CEPS 1e-5f

// ---------------- scratch (static device globals; no allocation) ----------------
__device__ float g_xx  [BB * NP];
__device__ int   g_idx [BB * NP * KNN];
__device__ float g_A   [BB * CH * NP];
__device__ float g_Bt  [BB * CH * NP];
__device__ float g_Y1  [(size_t)BB * CH * NP * KNN];   // 167.8 MB
__device__ float g_Y2  [(size_t)BB * CH * NP * KNN];   // 167.8 MB
__device__ float g_x1  [BB * CH * NP];
__device__ float g_x2  [BB * CH * NP];
__device__ float g_x3  [BB * CH * NP];
__device__ float g_st  [BB * 1024 * 2];                // mean, rstd per (b, ch)
__device__ float g_Y   [(size_t)BB * 1024 * NP];       // 134 MB
__device__ float g_pool[BB * 1024];

// ---------------- xx = sum_c f^2 ----------------
template<int C>
__global__ void xx_kernel(const float* __restrict__ f, float* __restrict__ xx) {
    int i = blockIdx.x * blockDim.x + threadIdx.x;
    if (i >= BB * NP) return;
    int b = i / NP, n = i % NP;
    const float* fb = f + (size_t)b * C * NP + n;
    float s = 0.f;
#pragma unroll
    for (int c = 0; c < C; c++) { float v = fb[(size_t)c * NP]; s += v * v; }
    xx[i] = s;
}

// ---------------- fused knn: distances + top-K selection ----------------
// d(m) = 2*<f_n, f_m> - xx[m]  (ranking identical to pd; -xx[n] is a per-row constant)
template<int C>
__global__ __launch_bounds__(128)
void knn_kernel(const float* __restrict__ f, const float* __restrict__ xx,
                int* __restrict__ idxout) {
    const int TQ = 128;
    __shared__ float smc[TQ * C];   // candidate tile [j][C]
    __shared__ float smxx[TQ];
    int b = blockIdx.y;
    int n = blockIdx.x * TQ + threadIdx.x;
    const float* fb = f + (size_t)b * C * NP;

    float q[C];
#pragma unroll
    for (int c = 0; c < C; c++) q[c] = fb[(size_t)c * NP + n];

    float vals[KNN];
    int   inds[KNN];
#pragma unroll
    for (int k = 0; k < KNN; k++) { vals[k] = -3.4e38f; inds[k] = 0; }
    float minv = -3.4e38f;

    for (int m0 = 0; m0 < NP; m0 += TQ) {
        __syncthreads();
        for (int i = threadIdx.x; i < TQ * C; i += TQ) {
            int c = i / TQ, j = i % TQ;              // coalesced global read over j
            smc[j * C + c] = fb[(size_t)c * NP + m0 + j];
        }
        smxx[threadIdx.x] = xx[b * NP + m0 + threadIdx.x];
        __syncthreads();

#pragma unroll 2
        for (int j = 0; j < TQ; j++) {
            const float* cj = &smc[j * C];
            float dot = 0.f;
#pragma unroll
            for (int c = 0; c < C; c++) dot += q[c] * cj[c];
            float d = 2.f * dot - smxx[j];
            if (d > minv) {
                int p = KNN - 1;
                while (p > 0 && d > vals[p - 1]) {
                    vals[p] = vals[p - 1]; inds[p] = inds[p - 1]; p--;
                }
                vals[p] = d; inds[p] = m0 + j;
                minv = vals[KNN - 1];
            }
        }
    }
    int* op = idxout + ((size_t)b * NP + n) * KNN;
#pragma unroll
    for (int k = 0; k < KNN; k++) op[k] = inds[k];
}

// ---------------- point transform: A = Wl@f, Bt = (Wr-Wl)@f ----------------
template<int C>
__global__ void pt_kernel(const float* __restrict__ f, const float* __restrict__ Wa,
                          float* __restrict__ A, float* __restrict__ Bt) {
    int i = blockIdx.x * blockDim.x + threadIdx.x;
    if (i >= BB * CH * NP) return;
    int n = i % NP, o = (i / NP) % CH, b = i / (NP * CH);
    const float* fb = f + (size_t)b * C * NP + n;
    const float* w  = Wa + o * 2 * C;
    float a = 0.f, bm = 0.f;
#pragma unroll
    for (int c = 0; c < C; c++) {
        float v = fb[(size_t)c * NP];
        a  += w[c] * v;
        bm += (w[C + c] - w[c]) * v;
    }
    A[i] = a; Bt[i] = bm;
}

// ---------------- y1[bo][n][k] = A[bo][idx[n,k]] + Bt[bo][n] ----------------
__global__ void y1_kernel(const float* __restrict__ A, const float* __restrict__ Bt,
                          const int* __restrict__ idx, float* __restrict__ Y1) {
    __shared__ float sA[NP];                    // 16 KB: full A plane for this (b,o)
    int bo = blockIdx.y;
    int b  = bo / CH;
    for (int i = threadIdx.x; i < NP; i += blockDim.x)
        sA[i] = A[(size_t)bo * NP + i];
    __syncthreads();
    int n0 = blockIdx.x * 512;
    const int*  ib = idx + ((size_t)b * NP + n0) * KNN;
    const float* bt = Bt + (size_t)bo * NP + n0;
    float* y = Y1 + ((size_t)bo * NP + n0) * KNN;
    for (int i = threadIdx.x; i < 512 * KNN; i += blockDim.x) {
        int nl = i / KNN;
        y[i] = sA[ib[i]] + bt[nl];
    }
}

// ---------------- per-channel mean / rstd (one block per channel) ----------------
__global__ void stats_kernel(const float* __restrict__ src, float* __restrict__ stats, int P) {
    int ch = blockIdx.x;
    const float* p = src + (size_t)ch * P;
    double s = 0.0, s2 = 0.0;
    for (int i = threadIdx.x; i < P; i += 256) {
        float v = p[i]; s += v; s2 += (double)v * v;
    }
    __shared__ double sh[512];
    sh[threadIdx.x] = s; sh[256 + threadIdx.x] = s2;
    __syncthreads();
    for (int st = 128; st > 0; st >>= 1) {
        if (threadIdx.x < st) {
            sh[threadIdx.x]       += sh[threadIdx.x + st];
            sh[256 + threadIdx.x] += sh[256 + threadIdx.x + st];
        }
        __syncthreads();
    }
    if (threadIdx.x == 0) {
        double m   = sh[0] / P;
        double var = sh[256] / P - m * m;
        stats[ch * 2]     = (float)m;
        stats[ch * 2 + 1] = (float)(1.0 / sqrt(var + (double)CEPS));
    }
}

// ---------------- conv2: y2 = Wb @ lrelu(inorm(y1)) ----------------
__global__ __launch_bounds__(128)
void conv2_kernel(const float* __restrict__ Y1, const float* __restrict__ Wb,
                  const float* __restrict__ stats, float* __restrict__ Y2) {
    const int P = NP * KNN;
    __shared__ float sW[CH * CH];
    __shared__ float sm[CH], sr[CH];
    int b = blockIdx.y;
    for (int i = threadIdx.x; i < CH * CH; i += 128) sW[i] = Wb[i];
    if (threadIdx.x < CH) {
        sm[threadIdx.x] = stats[(b * CH + threadIdx.x) * 2];
        sr[threadIdx.x] = stats[(b * CH + threadIdx.x) * 2 + 1];
    }
    __syncthreads();
    int p = blockIdx.x * 128 + threadIdx.x;
    float acc[CH];
#pragma unroll
    for (int o = 0; o < CH; o++) acc[o] = 0.f;
    const float* y1 = Y1 + (size_t)b * CH * P + p;
#pragma unroll 4
    for (int c = 0; c < CH; c++) {
        float v = y1[(size_t)c * P];
        v = (v - sm[c]) * sr[c];
        v = v > 0.f ? v : 0.2f * v;
#pragma unroll
        for (int o = 0; o < CH; o++) acc[o] += sW[o * CH + c] * v;
    }
    float* y2 = Y2 + (size_t)b * CH * P + p;
#pragma unroll
    for (int o = 0; o < CH; o++) y2[(size_t)o * P] = acc[o];
}

// ---------------- max over K of lrelu(inorm(y2)) ----------------
__global__ void maxk_kernel(const float* __restrict__ Y2, const float* __restrict__ stats,
                            float* __restrict__ xout) {
    int i = blockIdx.x * blockDim.x + threadIdx.x;   // over B*CH*NP
    if (i >= BB * CH * NP) return;
    int bo = i / NP;
    float m = stats[bo * 2], r = stats[bo * 2 + 1];
    const float* y = Y2 + (size_t)i * KNN;
    float mx = -3.4e38f;
#pragma unroll
    for (int k = 0; k < KNN; k++) {
        float v = (y[k] - m) * r;
        v = v > 0.f ? v : 0.2f * v;
        mx = fmaxf(mx, v);
    }
    xout[i] = mx;
}

// ---------------- final GEMM: Y[b, o, n] = Ws[o, :] @ concat(x1,x2,x3)[b, :, n] ----------------
__global__ __launch_bounds__(128)
void fgemm_kernel(const float* __restrict__ x1, const float* __restrict__ x2,
                  const float* __restrict__ x3, const float* __restrict__ Ws,
                  float* __restrict__ Y) {
    __shared__ float sW[64 * 192];                 // 48 KB
    int b  = blockIdx.z;
    int o0 = blockIdx.y * 64;
    int n  = blockIdx.x * 128 + threadIdx.x;
    for (int i = threadIdx.x; i < 64 * 192; i += 128) {
        int o = i / 192, c = i % 192;
        sW[i] = Ws[(size_t)(o0 + o) * 192 + c];
    }
    __syncthreads();
    float acc[64];
#pragma unroll
    for (int o = 0; o < 64; o++) acc[o] = 0.f;
    const float* srcs[3] = { x1 + (size_t)b * CH * NP + n,
                             x2 + (size_t)b * CH * NP + n,
                             x3 + (size_t)b * CH * NP + n };
    for (int g = 0; g < 3; g++) {
        const float* s = srcs[g];
#pragma unroll 4
        for (int c = 0; c < 64; c++) {
            float v = s[(size_t)c * NP];
            int cc = g * 64 + c;
#pragma unroll
            for (int o = 0; o < 64; o++) acc[o] += sW[o * 192 + cc] * v;
        }
    }
    float* y = Y + ((size_t)b * 1024 + o0) * NP + n;
#pragma unroll
    for (int o = 0; o < 64; o++) y[(size_t)o * NP] = acc[o];
}

// ---------------- global max pool of lrelu(inorm(Y)) ----------------
__global__ void pool_kernel(const float* __restrict__ Y, const float* __restrict__ stats,
                            float* __restrict__ pool) {
    int ch = blockIdx.x;            // b*1024 + o
    float m = stats[ch * 2], r = stats[ch * 2 + 1];
    const float* y = Y + (size_t)ch * NP;
    float mx = -3.4e38f;
    for (int i = threadIdx.x; i < NP; i += 128) {
        float v = (y[i] - m) * r;
        v = v > 0.f ? v : 0.2f * v;
        mx = fmaxf(mx, v);
    }
    __shared__ float sh[128];
    sh[threadIdx.x] = mx; __syncthreads();
    for (int st = 64; st > 0; st >>= 1) {
        if (threadIdx.x < st) sh[threadIdx.x] = fmaxf(sh[threadIdx.x], sh[threadIdx.x + st]);
        __syncthreads();
    }
    if (threadIdx.x == 0) pool[ch] = sh[0];
}

// ---------------- assemble output: [pool bcast | x1 | x2 | x3] ----------------
__global__ void out_kernel(const float* __restrict__ pool, const float* __restrict__ x1,
                           const float* __restrict__ x2, const float* __restrict__ x3,
                           float* __restrict__ out) {
    size_t i = (size_t)blockIdx.x * blockDim.x + threadIdx.x;
    const size_t total = (size_t)BB * 1216 * NP;
    if (i >= total) return;
    int n  = (int)(i % NP);
    int ch = (int)((i / NP) % 1216);
    int b  = (int)(i / ((size_t)NP * 1216));
    float v;
    if (ch < 1024) {
        v = pool[b * 1024 + ch];
    } else {
        int c2 = ch - 1024;
        const float* s = (c2 < 64) ? x1 : (c2 < 128 ? x2 : x3);
        v = s[((size_t)b * CH + (c2 & 63)) * NP + n];
    }
    out[i] = v;
}

// ---------------- orchestration ----------------
static void run_edge_layer_c3(const float* f, const float* Wa, const float* Wb, float* xout,
                              float* xxp, int* idxp, float* Ap, float* Btp,
                              float* Y1p, float* Y2p, float* stp) {
    xx_kernel<3><<<(BB * NP + 255) / 256, 256>>>(f, xxp);
    knn_kernel<3><<<dim3(NP / 128, BB), 128>>>(f, xxp, idxp);
    pt_kernel<3><<<(BB * CH * NP + 255) / 256, 256>>>(f, Wa, Ap, Btp);
    y1_kernel<<<dim3(NP / 512, BB * CH), 256>>>(Ap, Btp, idxp, Y1p);
    stats_kernel<<<BB * CH, 256>>>(Y1p, stp, NP * KNN);
    conv2_kernel<<<dim3(NP * KNN / 128, BB), 128>>>(Y1p, Wb, stp, Y2p);
    stats_kernel<<<BB * CH, 256>>>(Y2p, stp, NP * KNN);
    maxk_kernel<<<(BB * CH * NP + 255) / 256, 256>>>(Y2p, stp, xout);
}

static void run_edge_layer_c64(const float* f, const float* Wa, const float* Wb, float* xout,
                               float* xxp, int* idxp, float* Ap, float* Btp,
                               float* Y1p, float* Y2p, float* stp) {
    xx_kernel<CH><<<(BB * NP + 255) / 256, 256>>>(f, xxp);
    knn_kernel<CH><<<dim3(NP / 128, BB), 128>>>(f, xxp, idxp);
    pt_kernel<CH><<<(BB * CH * NP + 255) / 256, 256>>>(f, Wa, Ap, Btp);
    y1_kernel<<<dim3(NP / 512, BB * CH), 256>>>(Ap, Btp, idxp, Y1p);
    stats_kernel<<<BB * CH, 256>>>(Y1p, stp, NP * KNN);
    conv2_kernel<<<dim3(NP * KNN / 128, BB), 128>>>(Y1p, Wb, stp, Y2p);
    stats_kernel<<<BB * CH, 256>>>(Y2p, stp, NP * KNN);
    maxk_kernel<<<(BB * CH * NP + 255) / 256, 256>>>(Y2p, stp, xout);
}

extern "C" void kernel_launch(void* const* d_in, const int* in_sizes, int n_in,
                              void* d_out, int out_size) {
    const float* x   = (const float*)d_in[0];
    const float* W0a = (const float*)d_in[1];
    const float* W0b = (const float*)d_in[2];
    const float* W1a = (const float*)d_in[3];
    const float* W1b = (const float*)d_in[4];
    const float* W2a = (const float*)d_in[5];
    const float* W2b = (const float*)d_in[6];
    const float* Ws  = (const float*)d_in[7];
    float* out = (float*)d_out;

    float *xxp, *Ap, *Btp, *Y1p, *Y2p, *x1p, *x2p, *x3p, *stp, *Yp, *poolp;
    int* idxp;
    cudaGetSymbolAddress((void**)&xxp,   g_xx);
    cudaGetSymbolAddress((void**)&idxp,  g_idx);
    cudaGetSymbolAddress((void**)&Ap,    g_A);
    cudaGetSymbolAddress((void**)&Btp,   g_Bt);
    cudaGetSymbolAddress((void**)&Y1p,   g_Y1);
    cudaGetSymbolAddress((void**)&Y2p,   g_Y2);
    cudaGetSymbolAddress((void**)&x1p,   g_x1);
    cudaGetSymbolAddress((void**)&x2p,   g_x2);
    cudaGetSymbolAddress((void**)&x3p,   g_x3);
    cudaGetSymbolAddress((void**)&stp,   g_st);
    cudaGetSymbolAddress((void**)&Yp,    g_Y);
    cudaGetSymbolAddress((void**)&poolp, g_pool);

    run_edge_layer_c3 (x,   W0a, W0b, x1p, xxp, idxp, Ap, Btp, Y1p, Y2p, stp);
    run_edge_layer_c64(x1p, W1a, W1b, x2p, xxp, idxp, Ap, Btp, Y1p, Y2p, stp);
    run_edge_layer_c64(x2p, W2a, W2b, x3p, xxp, idxp, Ap, Btp, Y1p, Y2p, stp);

    fgemm_kernel<<<dim3(NP / 128, 1024 / 64, BB), 128>>>(x1p, x2p, x3p, Ws, Yp);
    stats_kernel<<<BB * 1024, 256>>>(Yp, stp, NP);
    pool_kernel<<<BB * 1024, 128>>>(Yp, stp, poolp);

    const size_t total = (size_t)BB * 1216 * NP;
    out_kernel<<<(unsigned)((total + 255) / 256), 256>>>(poolp, x1p, x2p, x3p, out);
}

// round 4
// speedup vs baseline: 1.1732x; 1.1732x over previous
#include <cuda_runtime.h>
#include <cuda_bf16.h>
#include <cstdint>

#define BB   8
#define NP   4096
#define KNN  20
#define CH   64
#define CEPS 1e-5f

// ---------------- scratch (static device globals; no allocation) ----------------
__device__ float g_xx  [BB * NP];
__device__ int   g_idx [BB * NP * KNN];
__device__ float g_A   [BB * CH * NP];
__device__ float g_Bt  [BB * CH * NP];
__device__ float g_Y1  [(size_t)BB * CH * NP * KNN];   // 167.8 MB
__device__ float g_Y2  [(size_t)BB * CH * NP * KNN];   // 167.8 MB
__device__ float g_x1  [BB * CH * NP];
__device__ float g_x2  [BB * CH * NP];
__device__ float g_x3  [BB * CH * NP];
__device__ float g_st  [BB * 1024 * 2];                // mean, rstd per (b, ch)
__device__ float g_Y   [(size_t)BB * 1024 * NP];       // 134 MB
__device__ float g_pool[BB * 1024];

// ---------------- xx = sum_c f^2 ----------------
template<int C>
__global__ void xx_kernel(const float* __restrict__ f, float* __restrict__ xx) {
    int i = blockIdx.x * blockDim.x + threadIdx.x;
    if (i >= BB * NP) return;
    int b = i / NP, n = i % NP;
    const float* fb = f + (size_t)b * C * NP + n;
    float s = 0.f;
#pragma unroll
    for (int c = 0; c < C; c++) { float v = fb[(size_t)c * NP]; s += v * v; }
    xx[i] = s;
}

// ---------------- fused knn: distances + top-K selection ----------------
template<int C>
__global__ __launch_bounds__(128)
void knn_kernel(const float* __restrict__ f, const float* __restrict__ xx,
                int* __restrict__ idxout) {
    const int TQ = 128;
    __shared__ float smc[TQ * C];   // candidate tile [j][C]
    __shared__ float smxx[TQ];
    int b = blockIdx.y;
    int n = blockIdx.x * TQ + threadIdx.x;
    const float* fb = f + (size_t)b * C * NP;

    float q[C];
#pragma unroll
    for (int c = 0; c < C; c++) q[c] = fb[(size_t)c * NP + n];

    float vals[KNN];
    int   inds[KNN];
#pragma unroll
    for (int k = 0; k < KNN; k++) { vals[k] = -3.4e38f; inds[k] = 0; }
    float minv = -3.4e38f;

    for (int m0 = 0; m0 < NP; m0 += TQ) {
        __syncthreads();
        for (int i = threadIdx.x; i < TQ * C; i += TQ) {
            int c = i / TQ, j = i % TQ;              // coalesced global read over j
            smc[j * C + c] = fb[(size_t)c * NP + m0 + j];
        }
        smxx[threadIdx.x] = xx[b * NP + m0 + threadIdx.x];
        __syncthreads();

#pragma unroll 2
        for (int j = 0; j < TQ; j++) {
            const float* cj = &smc[j * C];
            float dot = 0.f;
#pragma unroll
            for (int c = 0; c < C; c++) dot += q[c] * cj[c];
            float d = 2.f * dot - smxx[j];
            if (d > minv) {
                int p = KNN - 1;
                while (p > 0 && d > vals[p - 1]) {
                    vals[p] = vals[p - 1]; inds[p] = inds[p - 1]; p--;
                }
                vals[p] = d; inds[p] = m0 + j;
                minv = vals[KNN - 1];
            }
        }
    }
    int* op = idxout + ((size_t)b * NP + n) * KNN;
#pragma unroll
    for (int k = 0; k < KNN; k++) op[k] = inds[k];
}

// ---------------- point transform: A = Wl@f, Bt = (Wr-Wl)@f ----------------
template<int C>
__global__ void pt_kernel(const float* __restrict__ f, const float* __restrict__ Wa,
                          float* __restrict__ A, float* __restrict__ Bt) {
    int i = blockIdx.x * blockDim.x + threadIdx.x;
    if (i >= BB * CH * NP) return;
    int n = i % NP, o = (i / NP) % CH, b = i / (NP * CH);
    const float* fb = f + (size_t)b * C * NP + n;
    const float* w  = Wa + o * 2 * C;
    float a = 0.f, bm = 0.f;
#pragma unroll
    for (int c = 0; c < C; c++) {
        float v = fb[(size_t)c * NP];
        a  += w[c] * v;
        bm += (w[C + c] - w[c]) * v;
    }
    A[i] = a; Bt[i] = bm;
}

// ---------------- y1[bo][n][k] = A[bo][idx[n,k]] + Bt[bo][n] ----------------
__global__ void y1_kernel(const float* __restrict__ A, const float* __restrict__ Bt,
                          const int* __restrict__ idx, float* __restrict__ Y1) {
    __shared__ float sA[NP];                    // 16 KB: full A plane for this (b,o)
    int bo = blockIdx.y;
    int b  = bo / CH;
    for (int i = threadIdx.x; i < NP; i += blockDim.x)
        sA[i] = A[(size_t)bo * NP + i];
    __syncthreads();
    int n0 = blockIdx.x * 512;
    const int*  ib = idx + ((size_t)b * NP + n0) * KNN;
    const float* bt = Bt + (size_t)bo * NP + n0;
    float* y = Y1 + ((size_t)bo * NP + n0) * KNN;
    for (int i = threadIdx.x; i < 512 * KNN; i += blockDim.x) {
        int nl = i / KNN;
        y[i] = sA[ib[i]] + bt[nl];
    }
}

// ---------------- per-channel mean / rstd (fp32, vectorized, one block/channel) ----------------
__global__ __launch_bounds__(256)
void stats_kernel(const float* __restrict__ src, float* __restrict__ stats, int P) {
    int ch = blockIdx.x;
    const float4* p = (const float4*)(src + (size_t)ch * P);
    int P4 = P >> 2;
    float sx = 0.f, sy = 0.f, sz = 0.f, sw = 0.f;
    float qx = 0.f, qy = 0.f, qz = 0.f, qw = 0.f;
    for (int i = threadIdx.x; i < P4; i += 256) {
        float4 v = p[i];
        sx += v.x; sy += v.y; sz += v.z; sw += v.w;
        qx += v.x * v.x; qy += v.y * v.y; qz += v.z * v.z; qw += v.w * v.w;
    }
    float s  = (sx + sy) + (sz + sw);
    float s2 = (qx + qy) + (qz + qw);
    __shared__ float sh[512];
    sh[threadIdx.x] = s; sh[256 + threadIdx.x] = s2;
    __syncthreads();
    for (int st = 128; st > 0; st >>= 1) {
        if (threadIdx.x < st) {
            sh[threadIdx.x]       += sh[threadIdx.x + st];
            sh[256 + threadIdx.x] += sh[256 + threadIdx.x + st];
        }
        __syncthreads();
    }
    if (threadIdx.x == 0) {
        float m   = sh[0] / (float)P;
        float var = sh[256] / (float)P - m * m;
        stats[ch * 2]     = m;
        stats[ch * 2 + 1] = rsqrtf(var + CEPS);
    }
}

// ---------------- conv2: y2 = Wb @ lrelu(inorm(y1)), 2 points/thread ----------------
__global__ __launch_bounds__(128)
void conv2_kernel(const float* __restrict__ Y1, const float* __restrict__ Wb,
                  const float* __restrict__ stats, float* __restrict__ Y2) {
    const int P = NP * KNN;
    __shared__ float sWt[CH * CH];      // transposed: [c][o]
    __shared__ float sm[CH], sr[CH];
    int b = blockIdx.y;
    for (int i = threadIdx.x; i < CH * CH; i += 128) {
        int c = i >> 6, o = i & 63;
        sWt[c * CH + o] = Wb[o * CH + c];
    }
    if (threadIdx.x < CH) {
        sm[threadIdx.x] = stats[(b * CH + threadIdx.x) * 2];
        sr[threadIdx.x] = stats[(b * CH + threadIdx.x) * 2 + 1];
    }
    __syncthreads();
    int p0 = blockIdx.x * 256 + threadIdx.x;
    int p1 = p0 + 128;
    float acc0[CH], acc1[CH];
#pragma unroll
    for (int o = 0; o < CH; o++) { acc0[o] = 0.f; acc1[o] = 0.f; }
    const float* y1 = Y1 + (size_t)b * CH * P;
#pragma unroll 2
    for (int c = 0; c < CH; c++) {
        float v0 = y1[(size_t)c * P + p0];
        float v1 = y1[(size_t)c * P + p1];
        float m = sm[c], r = sr[c];
        v0 = (v0 - m) * r; v0 = v0 > 0.f ? v0 : 0.2f * v0;
        v1 = (v1 - m) * r; v1 = v1 > 0.f ? v1 : 0.2f * v1;
        const float4* w = (const float4*)&sWt[c * CH];
#pragma unroll
        for (int o4 = 0; o4 < 16; o4++) {
            float4 w4 = w[o4];
            acc0[4*o4+0] += w4.x * v0; acc1[4*o4+0] += w4.x * v1;
            acc0[4*o4+1] += w4.y * v0; acc1[4*o4+1] += w4.y * v1;
            acc0[4*o4+2] += w4.z * v0; acc1[4*o4+2] += w4.z * v1;
            acc0[4*o4+3] += w4.w * v0; acc1[4*o4+3] += w4.w * v1;
        }
    }
    float* y2 = Y2 + (size_t)b * CH * P;
#pragma unroll
    for (int o = 0; o < CH; o++) {
        y2[(size_t)o * P + p0] = acc0[o];
        y2[(size_t)o * P + p1] = acc1[o];
    }
}

// ---------------- max over K of lrelu(inorm(y2)) ----------------
__global__ void maxk_kernel(const float* __restrict__ Y2, const float* __restrict__ stats,
                            float* __restrict__ xout) {
    int i = blockIdx.x * blockDim.x + threadIdx.x;   // over B*CH*NP
    if (i >= BB * CH * NP) return;
    int bo = i / NP;
    float m = stats[bo * 2], r = stats[bo * 2 + 1];
    const float4* y = (const float4*)(Y2 + (size_t)i * KNN);
    float mx = -3.4e38f;
#pragma unroll
    for (int k4 = 0; k4 < 5; k4++) {
        float4 v = y[k4];
        mx = fmaxf(mx, fmaxf(fmaxf(v.x, v.y), fmaxf(v.z, v.w)));
    }
    float v = (mx - m) * r;          // max commutes with the monotone affine map (r>0)
    v = v > 0.f ? v : 0.2f * v;
    xout[i] = v;
}

// ---------------- final GEMM: Y[b, o, n] = Ws[o, :] @ concat(x1,x2,x3)[b, :, n] ----------------
__global__ __launch_bounds__(128)
void fgemm_kernel(const float* __restrict__ x1, const float* __restrict__ x2,
                  const float* __restrict__ x3, const float* __restrict__ Ws,
                  float* __restrict__ Y) {
    __shared__ float sWt[192 * 64];                // transposed [c][o], 48 KB
    int b  = blockIdx.z;
    int o0 = blockIdx.y * 64;
    int n0 = blockIdx.x * 256 + threadIdx.x;
    int n1 = n0 + 128;
    for (int i = threadIdx.x; i < 192 * 64; i += 128) {
        int c = i >> 6, o = i & 63;
        sWt[c * 64 + o] = Ws[(size_t)(o0 + o) * 192 + c];
    }
    __syncthreads();
    float acc0[64], acc1[64];
#pragma unroll
    for (int o = 0; o < 64; o++) { acc0[o] = 0.f; acc1[o] = 0.f; }
    const float* srcs[3] = { x1 + (size_t)b * CH * NP,
                             x2 + (size_t)b * CH * NP,
                             x3 + (size_t)b * CH * NP };
    for (int g = 0; g < 3; g++) {
        const float* s = srcs[g];
#pragma unroll 2
        for (int c = 0; c < 64; c++) {
            float v0 = s[(size_t)c * NP + n0];
            float v1 = s[(size_t)c * NP + n1];
            const float4* w = (const float4*)&sWt[(g * 64 + c) * 64];
#pragma unroll
            for (int o4 = 0; o4 < 16; o4++) {
                float4 w4 = w[o4];
                acc0[4*o4+0] += w4.x * v0; acc1[4*o4+0] += w4.x * v1;
                acc0[4*o4+1] += w4.y * v0; acc1[4*o4+1] += w4.y * v1;
                acc0[4*o4+2] += w4.z * v0; acc1[4*o4+2] += w4.z * v1;
                acc0[4*o4+3] += w4.w * v0; acc1[4*o4+3] += w4.w * v1;
            }
        }
    }
    float* y = Y + ((size_t)b * 1024 + o0) * NP;
#pragma unroll
    for (int o = 0; o < 64; o++) {
        y[(size_t)o * NP + n0] = acc0[o];
        y[(size_t)o * NP + n1] = acc1[o];
    }
}

// ---------------- global max pool of lrelu(inorm(Y)) ----------------
__global__ void pool_kernel(const float* __restrict__ Y, const float* __restrict__ stats,
                            float* __restrict__ pool) {
    int ch = blockIdx.x;            // b*1024 + o
    float m = stats[ch * 2], r = stats[ch * 2 + 1];
    const float4* y = (const float4*)(Y + (size_t)ch * NP);
    float mx = -3.4e38f;
    for (int i = threadIdx.x; i < NP / 4; i += 128) {
        float4 v = y[i];
        mx = fmaxf(mx, fmaxf(fmaxf(v.x, v.y), fmaxf(v.z, v.w)));
    }
    __shared__ float sh[128];
    sh[threadIdx.x] = mx; __syncthreads();
    for (int st = 64; st > 0; st >>= 1) {
        if (threadIdx.x < st) sh[threadIdx.x] = fmaxf(sh[threadIdx.x], sh[threadIdx.x + st]);
        __syncthreads();
    }
    if (threadIdx.x == 0) {
        float v = (sh[0] - m) * r;   // max commutes with monotone affine map (r>0)
        v = v > 0.f ? v : 0.2f * v;
        pool[ch] = v;
    }
}

// ---------------- assemble output: [pool bcast | x1 | x2 | x3] ----------------
__global__ void out_kernel(const float* __restrict__ pool, const float* __restrict__ x1,
                           const float* __restrict__ x2, const float* __restrict__ x3,
                           float* __restrict__ out) {
    size_t i = (size_t)blockIdx.x * blockDim.x + threadIdx.x;
    const size_t total = (size_t)BB * 1216 * NP;
    if (i >= total) return;
    int n  = (int)(i % NP);
    int ch = (int)((i / NP) % 1216);
    int b  = (int)(i / ((size_t)NP * 1216));
    float v;
    if (ch < 1024) {
        v = pool[b * 1024 + ch];
    } else {
        int c2 = ch - 1024;
        const float* s = (c2 < 64) ? x1 : (c2 < 128 ? x2 : x3);
        v = s[((size_t)b * CH + (c2 & 63)) * NP + n];
    }
    out[i] = v;
}

// ---------------- orchestration ----------------
template<int C>
static void run_edge_layer(const float* f, const float* Wa, const float* Wb, float* xout,
                           float* xxp, int* idxp, float* Ap, float* Btp,
                           float* Y1p, float* Y2p, float* stp) {
    xx_kernel<C><<<(BB * NP + 255) / 256, 256>>>(f, xxp);
    knn_kernel<C><<<dim3(NP / 128, BB), 128>>>(f, xxp, idxp);
    pt_kernel<C><<<(BB * CH * NP + 255) / 256, 256>>>(f, Wa, Ap, Btp);
    y1_kernel<<<dim3(NP / 512, BB * CH), 256>>>(Ap, Btp, idxp, Y1p);
    stats_kernel<<<BB * CH, 256>>>(Y1p, stp, NP * KNN);
    conv2_kernel<<<dim3(NP * KNN / 256, BB), 128>>>(Y1p, Wb, stp, Y2p);
    stats_kernel<<<BB * CH, 256>>>(Y2p, stp, NP * KNN);
    maxk_kernel<<<(BB * CH * NP + 255) / 256, 256>>>(Y2p, stp, xout);
}

extern "C" void kernel_launch(void* const* d_in, const int* in_sizes, int n_in,
                              void* d_out, int out_size) {
    const float* x   = (const float*)d_in[0];
    const float* W0a = (const float*)d_in[1];
    const float* W0b = (const float*)d_in[2];
    const float* W1a = (const float*)d_in[3];
    const float* W1b = (const float*)d_in[4];
    const float* W2a = (const float*)d_in[5];
    const float* W2b = (const float*)d_in[6];
    const float* Ws  = (const float*)d_in[7];
    float* out = (float*)d_out;

    float *xxp, *Ap, *Btp, *Y1p, *Y2p, *x1p, *x2p, *x3p, *stp, *Yp, *poolp;
    int* idxp;
    cudaGetSymbolAddress((void**)&xxp,   g_xx);
    cudaGetSymbolAddress((void**)&idxp,  g_idx);
    cudaGetSymbolAddress((void**)&Ap,    g_A);
    cudaGetSymbolAddress((void**)&Btp,   g_Bt);
    cudaGetSymbolAddress((void**)&Y1p,   g_Y1);
    cudaGetSymbolAddress((void**)&Y2p,   g_Y2);
    cudaGetSymbolAddress((void**)&x1p,   g_x1);
    cudaGetSymbolAddress((void**)&x2p,   g_x2);
    cudaGetSymbolAddress((void**)&x3p,   g_x3);
    cudaGetSymbolAddress((void**)&stp,   g_st);
    cudaGetSymbolAddress((void**)&Yp,    g_Y);
    cudaGetSymbolAddress((void**)&poolp, g_pool);

    run_edge_layer<3> (x,   W0a, W0b, x1p, xxp, idxp, Ap, Btp, Y1p, Y2p, stp);
    run_edge_layer<CH>(x1p, W1a, W1b, x2p, xxp, idxp, Ap, Btp, Y1p, Y2p, stp);
    run_edge_layer<CH>(x2p, W2a, W2b, x3p, xxp, idxp, Ap, Btp, Y1p, Y2p, stp);

    fgemm_kernel<<<dim3(NP / 256, 1024 / 64, BB), 128>>>(x1p, x2p, x3p, Ws, Yp);
    stats_kernel<<<BB * 1024, 256>>>(Yp, stp, NP);
    pool_kernel<<<BB * 1024, 128>>>(Yp, stp, poolp);

    const size_t total = (size_t)BB * 1216 * NP;
    out_kernel<<<(unsigned)((total + 255) / 256), 256>>>(poolp, x1p, x2p, x3p, out);
}